// round 14
// baseline (speedup 1.0000x reference)
#include <cuda_runtime.h>
#include <cuda_bf16.h>

// DensityEstimator: per-channel 1->3->3->3->1 MLP, p = cdf(x+.5) - cdf(x-.5)
// R14: R13 body unchanged; ONLY the register bound. (128,7) let ptxas use 72
// regs -> still just 6 blocks = 24 warps (the same plateau as R6/R10).
// __launch_bounds__(128,8) FORCES <=64 regs (proven clean at 64 in R10) ->
// 7 blocks x 4 warps = 28 SMSP-balanced resident warps. Grid 1035 stays
// within capacity (no grid-stride wave quantization) and is divisible by 3
// so channel is fixed per thread (1035*128 = 192*690).

#define NCH  192
#define NBLK 1035
#define NTHR 128
#define NW   43

__device__ float g_wt[NW * NCH];   // transformed weights, [k][c]

__device__ __forceinline__ float tanha(float x) {
    float r; asm("tanh.approx.f32 %0, %1;" : "=f"(r) : "f"(x)); return r;
}
__device__ __forceinline__ float softplus_acc(float h) {
    return (h > 15.0f) ? h : log1pf(expf(h));
}

// ---- Kernel 1: data-parallel weight transform, one thread per weight ----
// k: 0-2 sh0 | 3-5 bp0 | 6-8 ta0 | 9-17 sh1 | 18-20 ta1 | 21-23 bb1
//    24-32 sh2 | 33-35 ta2 | 36-38 bb2 | 39-41 sh3(1/2) | 42 bb3(1/2)
__global__ void wt_kernel(
    const float* __restrict__ a0, const float* __restrict__ a1, const float* __restrict__ a2,
    const float* __restrict__ b0, const float* __restrict__ b1, const float* __restrict__ b2,
    const float* __restrict__ b3,
    const float* __restrict__ H0, const float* __restrict__ H1, const float* __restrict__ H2,
    const float* __restrict__ H3)
{
    int t = blockIdx.x * blockDim.x + threadIdx.x;
    if (t >= NW * NCH) return;
    int k = t / NCH;
    int c = t % NCH;
    float v;
    if      (k <  3) v = softplus_acc(H0[c*3 + k]);
    else if (k <  6) { int j = k - 3;
                       v = fmaf(0.5f, softplus_acc(H0[c*3 + j]), b0[c*3 + j]); }
    else if (k <  9) v = tanhf(a0[c*3 + (k - 6)]);
    else if (k < 18) v = softplus_acc(H1[c*9 + (k - 9)]);
    else if (k < 21) v = tanhf(a1[c*3 + (k - 18)]);
    else if (k < 24) v = b1[c*3 + (k - 21)];
    else if (k < 33) v = softplus_acc(H2[c*9 + (k - 24)]);
    else if (k < 36) v = tanhf(a2[c*3 + (k - 33)]);
    else if (k < 39) v = b2[c*3 + (k - 36)];
    else if (k < 42) v = 0.5f * softplus_acc(H3[c*3 + (k - 39)]);
    else             v = 0.5f * b3[c];
    g_wt[k * NCH + c] = v;
}

// ---- One element, both cdf branches (tm = tp - sh0[j], exact) ----
struct W {
    float sh0[3], bp0[3], ta0[3], sh1[9], ta1[3], bb1[3];
    float sh2[9], ta2[3], bb2[3], sh3[3], bb3;
};

__device__ __forceinline__ float de_one(float xv, const W& w) {
    float yp[3], ym[3];
#pragma unroll
    for (int j = 0; j < 3; j++) {
        float tp = fmaf(xv, w.sh0[j], w.bp0[j]);   // at x + 0.5
        float tm = tp - w.sh0[j];                  // at x - 0.5
        yp[j] = fmaf(w.ta0[j], tanha(tp), tp);
        ym[j] = fmaf(w.ta0[j], tanha(tm), tm);
    }
    float zp[3], zm[3];
#pragma unroll
    for (int p = 0; p < 3; p++) {
        float sp = w.bb1[p], sm = w.bb1[p];
#pragma unroll
        for (int j = 0; j < 3; j++) {
            sp = fmaf(yp[j], w.sh1[j*3 + p], sp);
            sm = fmaf(ym[j], w.sh1[j*3 + p], sm);
        }
        zp[p] = fmaf(w.ta1[p], tanha(sp), sp);
        zm[p] = fmaf(w.ta1[p], tanha(sm), sm);
    }
#pragma unroll
    for (int p = 0; p < 3; p++) {
        float sp = w.bb2[p], sm = w.bb2[p];
#pragma unroll
        for (int j = 0; j < 3; j++) {
            sp = fmaf(zp[j], w.sh2[j*3 + p], sp);
            sm = fmaf(zm[j], w.sh2[j*3 + p], sm);
        }
        yp[p] = fmaf(w.ta2[p], tanha(sp), sp);
        ym[p] = fmaf(w.ta2[p], tanha(sm), sm);
    }
    float fp = w.bb3, fm = w.bb3;
#pragma unroll
    for (int j = 0; j < 3; j++) {
        fp = fmaf(yp[j], w.sh3[j], fp);
        fm = fmaf(ym[j], w.sh3[j], fm);
    }
    return 0.5f * (tanha(fp) - tanha(fm));
}

// ---- Kernel 2: main evaluation, forced 64 regs -> 28 balanced warps/SM ----
__global__ void __launch_bounds__(NTHR, 8) de_kernel(
    const float* __restrict__ x, float* __restrict__ out, int n)
{
    const int T  = gridDim.x * blockDim.x;          // 132480, multiple of 192
    const int i0 = blockIdx.x * blockDim.x + threadIdx.x;
    const int c  = i0 % NCH;                        // fixed channel (T % 192 == 0)

    // 43 coalesced loads (lane-consecutive c), laundered via identity shfl.
    W w;
    float* wf = (float*)&w;
#pragma unroll
    for (int k = 0; k < NW; k++) {
        float v = g_wt[k * NCH + c];
        wf[k] = __shfl_sync(0xffffffffu, v, threadIdx.x & 31);
    }

    for (int i = i0; i < n; i += 2 * T) {
        const int  i2  = i + T;                     // same channel
        const bool ok2 = i2 < n;
        float xa = x[i];
        float xb = x[ok2 ? i2 : i];
        float ra = de_one(xa, w);
        float rb = de_one(xb, w);
        out[i] = ra;
        if (ok2) out[i2] = rb;
    }
}

extern "C" void kernel_launch(void* const* d_in, const int* in_sizes, int n_in,
                              void* d_out, int out_size)
{
    const float* x  = (const float*)d_in[0];
    const float* a0 = (const float*)d_in[1];
    const float* a1 = (const float*)d_in[2];
    const float* a2 = (const float*)d_in[3];
    const float* b0 = (const float*)d_in[4];
    const float* b1 = (const float*)d_in[5];
    const float* b2 = (const float*)d_in[6];
    const float* b3 = (const float*)d_in[7];
    const float* H0 = (const float*)d_in[8];
    const float* H1 = (const float*)d_in[9];
    const float* H2 = (const float*)d_in[10];
    const float* H3 = (const float*)d_in[11];
    float* out = (float*)d_out;
    int n = in_sizes[0];   // 65536 * 192

    wt_kernel<<<(NW * NCH + 255) / 256, 256>>>(
        a0, a1, a2, b0, b1, b2, b3, H0, H1, H2, H3);
    de_kernel<<<NBLK, NTHR>>>(x, out, n);
}

// round 16
// speedup vs baseline: 1.0164x; 1.0164x over previous
#include <cuda_runtime.h>
#include <cuda_bf16.h>

// DensityEstimator: per-channel 1->3->3->3->1 MLP, p = cdf(x+.5) - cdf(x-.5)
// R15b: same as R15 (compile fix: unsigned int instead of uint32_t).
// MUFU is the saturated pipe (20 tanh/elem x rt8 ~ 87% busy; occupancy knobs
// R11-R14 all flat). Cut MUFU ops: each hidden node needs tanh at two points
// (p and m branches) -> tanh.approx.f16x2 evaluates both in ONE MUFU op.
// Applied to layer 2 only (least downstream error amplification: halved sh3
// weights x sigmoid' <= 0.25). MUFU 20 -> 17/elem. Rest = R10 (82.0us best).

#define NCH  192
#define NBLK 591          // 591*256 = 151296 = 192*788
#define NTHR 256
#define NW   43

__device__ float g_wt[NW * NCH];   // transformed weights, [k][c]

__device__ __forceinline__ float tanha(float x) {
    float r; asm("tanh.approx.f32 %0, %1;" : "=f"(r) : "f"(x)); return r;
}
// Paired tanh via f16x2 MUFU: one MUFU op for both branch arguments.
// Pack compiles to F2FP/I2I-class ops, unpack to 2x F2F (ALU pipe, uncontended).
__device__ __forceinline__ void tanh2h(float ap, float am, float& tp, float& tm) {
    unsigned int pk, tk;
    asm("{\n\t.reg .b16 l, h;\n\t"
        "cvt.rn.f16.f32 l, %1;\n\t"
        "cvt.rn.f16.f32 h, %2;\n\t"
        "mov.b32 %0, {l, h};\n\t}" : "=r"(pk) : "f"(ap), "f"(am));
    asm("tanh.approx.f16x2 %0, %1;" : "=r"(tk) : "r"(pk));
    asm("{\n\t.reg .b16 l, h;\n\t"
        "mov.b32 {l, h}, %2;\n\t"
        "cvt.f32.f16 %0, l;\n\t"
        "cvt.f32.f16 %1, h;\n\t}" : "=f"(tp), "=f"(tm) : "r"(tk));
}
__device__ __forceinline__ float softplus_acc(float h) {
    return (h > 15.0f) ? h : log1pf(expf(h));
}

// ---- Kernel 1: data-parallel weight transform, one thread per weight ----
// k: 0-2 sh0 | 3-5 bp0 | 6-8 ta0 | 9-17 sh1 | 18-20 ta1 | 21-23 bb1
//    24-32 sh2 | 33-35 ta2 | 36-38 bb2 | 39-41 sh3(1/2) | 42 bb3(1/2)
__global__ void wt_kernel(
    const float* __restrict__ a0, const float* __restrict__ a1, const float* __restrict__ a2,
    const float* __restrict__ b0, const float* __restrict__ b1, const float* __restrict__ b2,
    const float* __restrict__ b3,
    const float* __restrict__ H0, const float* __restrict__ H1, const float* __restrict__ H2,
    const float* __restrict__ H3)
{
    int t = blockIdx.x * blockDim.x + threadIdx.x;
    if (t >= NW * NCH) return;
    int k = t / NCH;
    int c = t % NCH;
    float v;
    if      (k <  3) v = softplus_acc(H0[c*3 + k]);
    else if (k <  6) { int j = k - 3;
                       v = fmaf(0.5f, softplus_acc(H0[c*3 + j]), b0[c*3 + j]); }
    else if (k <  9) v = tanhf(a0[c*3 + (k - 6)]);
    else if (k < 18) v = softplus_acc(H1[c*9 + (k - 9)]);
    else if (k < 21) v = tanhf(a1[c*3 + (k - 18)]);
    else if (k < 24) v = b1[c*3 + (k - 21)];
    else if (k < 33) v = softplus_acc(H2[c*9 + (k - 24)]);
    else if (k < 36) v = tanhf(a2[c*3 + (k - 33)]);
    else if (k < 39) v = b2[c*3 + (k - 36)];
    else if (k < 42) v = 0.5f * softplus_acc(H3[c*3 + (k - 39)]);
    else             v = 0.5f * b3[c];
    g_wt[k * NCH + c] = v;
}

// ---- One element, both cdf branches (tm = tp - sh0[j], exact) ----
struct W {
    float sh0[3], bp0[3], ta0[3], sh1[9], ta1[3], bb1[3];
    float sh2[9], ta2[3], bb2[3], sh3[3], bb3;
};

__device__ __forceinline__ float de_one(float xv, const W& w) {
    float yp[3], ym[3];
#pragma unroll
    for (int j = 0; j < 3; j++) {
        float tp = fmaf(xv, w.sh0[j], w.bp0[j]);   // at x + 0.5
        float tm = tp - w.sh0[j];                  // at x - 0.5
        yp[j] = fmaf(w.ta0[j], tanha(tp), tp);
        ym[j] = fmaf(w.ta0[j], tanha(tm), tm);
    }
    float zp[3], zm[3];
#pragma unroll
    for (int p = 0; p < 3; p++) {
        float sp = w.bb1[p], sm = w.bb1[p];
#pragma unroll
        for (int j = 0; j < 3; j++) {
            sp = fmaf(yp[j], w.sh1[j*3 + p], sp);
            sm = fmaf(ym[j], w.sh1[j*3 + p], sm);
        }
        zp[p] = fmaf(w.ta1[p], tanha(sp), sp);
        zm[p] = fmaf(w.ta1[p], tanha(sm), sm);
    }
    // Layer 2: paired-branch tanh via one f16x2 MUFU op per node.
#pragma unroll
    for (int p = 0; p < 3; p++) {
        float sp = w.bb2[p], sm = w.bb2[p];
#pragma unroll
        for (int j = 0; j < 3; j++) {
            sp = fmaf(zp[j], w.sh2[j*3 + p], sp);
            sm = fmaf(zm[j], w.sh2[j*3 + p], sm);
        }
        float tp, tm;
        tanh2h(sp, sm, tp, tm);
        yp[p] = fmaf(w.ta2[p], tp, sp);
        ym[p] = fmaf(w.ta2[p], tm, sm);
    }
    float fp = w.bb3, fm = w.bb3;
#pragma unroll
    for (int j = 0; j < 3; j++) {
        fp = fmaf(yp[j], w.sh3[j], fp);
        fm = fmaf(ym[j], w.sh3[j], fm);
    }
    return 0.5f * (tanha(fp) - tanha(fm));
}

// ---- Kernel 2: main evaluation (R10 config) ----
__global__ void __launch_bounds__(NTHR, 4) de_kernel(
    const float* __restrict__ x, float* __restrict__ out, int n)
{
    const int T  = gridDim.x * blockDim.x;          // 151296, multiple of 192
    const int i0 = blockIdx.x * blockDim.x + threadIdx.x;
    const int c  = i0 % NCH;                        // fixed channel

    // 43 coalesced loads (lane-consecutive c), laundered via identity shfl.
    W w;
    float* wf = (float*)&w;
#pragma unroll
    for (int k = 0; k < NW; k++) {
        float v = g_wt[k * NCH + c];
        wf[k] = __shfl_sync(0xffffffffu, v, threadIdx.x & 31);
    }

    for (int i = i0; i < n; i += 2 * T) {
        const int  i2  = i + T;                     // same channel
        const bool ok2 = i2 < n;
        float xa = x[i];
        float xb = x[ok2 ? i2 : i];
        float ra = de_one(xa, w);
        float rb = de_one(xb, w);
        out[i] = ra;
        if (ok2) out[i2] = rb;
    }
}

extern "C" void kernel_launch(void* const* d_in, const int* in_sizes, int n_in,
                              void* d_out, int out_size)
{
    const float* x  = (const float*)d_in[0];
    const float* a0 = (const float*)d_in[1];
    const float* a1 = (const float*)d_in[2];
    const float* a2 = (const float*)d_in[3];
    const float* b0 = (const float*)d_in[4];
    const float* b1 = (const float*)d_in[5];
    const float* b2 = (const float*)d_in[6];
    const float* b3 = (const float*)d_in[7];
    const float* H0 = (const float*)d_in[8];
    const float* H1 = (const float*)d_in[9];
    const float* H2 = (const float*)d_in[10];
    const float* H3 = (const float*)d_in[11];
    float* out = (float*)d_out;
    int n = in_sizes[0];   // 65536 * 192

    wt_kernel<<<(NW * NCH + 255) / 256, 256>>>(
        a0, a1, a2, b0, b1, b2, b3, H0, H1, H2, H3);
    de_kernel<<<NBLK, NTHR>>>(x, out, n);
}